// round 2
// baseline (speedup 1.0000x reference)
#include <cuda_runtime.h>
#include <cuda_bf16.h>

#define BB 1024
#define TT 256
#define VV 256
#define HH 32

// hs scratch, layout [t][b][h]  (row r = t*B + b is contiguous 32 floats)
__device__ float g_hs[TT * BB * HH];

__device__ __forceinline__ float htanh(float x) {
    float y;
    asm("tanh.approx.f32 %0, %1;" : "=f"(y) : "f"(x));
    return y;
}

// ---------------------------------------------------------------------------
// Kernel A: embedding gather + recurrence.
// One warp per batch element, h[j] in lane j. Cross-lane h broadcast goes
// through a double-buffered SMEM vector (1 STS + 1 WARPSYNC + 8 LDS.128
// per step) instead of 32 SHFLs — MIO ops/step 32 -> 10.
// ---------------------------------------------------------------------------
__global__ void __launch_bounds__(256)
rnn_recurrence(const int* __restrict__ X, const float* __restrict__ Wxh,
               const float* __restrict__ Whh, const float* __restrict__ bh)
{
    __shared__ float sWxh[VV * HH];       // 32 KB
    __shared__ int   sX[8][TT];           // 8 KB
    __shared__ float sH[2][8][HH];        // 2 KB double-buffered h vectors

    const int tid  = threadIdx.x;
    const int lane = tid & 31;
    const int warp = tid >> 5;
    const int b    = blockIdx.x * 8 + warp;

    // stage W_xh
    {
        const float4* s = (const float4*)Wxh;
        float4*       d = (float4*)sWxh;
        #pragma unroll
        for (int i = tid; i < (VV * HH) / 4; i += 256) d[i] = s[i];
    }
    // stage this block's 8 token rows
    {
        const int4* s = (const int4*)(X + (long)blockIdx.x * 8 * TT);
        int4*       d = (int4*)&sX[0][0];
        #pragma unroll
        for (int i = tid; i < (8 * TT) / 4; i += 256) d[i] = s[i];
    }

    // W_hh column `lane` into registers: w[i] = Whh[i][lane]
    float w[HH];
    #pragma unroll
    for (int i = 0; i < HH; i++) w[i] = Whh[i * HH + lane];
    const float bhv = bh[lane];

    // h_0 = 0 into buffer 0
    sH[0][warp][lane] = 0.f;
    __syncthreads();

    float* outp = g_hs + (long)b * HH + lane;

    int   tok = sX[warp][0];
    float xe  = sWxh[tok * HH + lane];

    #pragma unroll 2
    for (int t = 0; t < TT; t++) {
        const int tokn = sX[warp][(t + 1) & (TT - 1)];  // prefetch next token

        // broadcast-read full h vector of previous step (buffer t&1)
        const float4* hr = (const float4*)&sH[t & 1][warp][0];
        float4 hv[8];
        #pragma unroll
        for (int k = 0; k < 8; k++) hv[k] = hr[k];

        float a0 = 0.f, a1 = 0.f, a2 = 0.f, a3 = 0.f;
        #pragma unroll
        for (int k = 0; k < 8; k++) {
            a0 = fmaf(hv[k].x, w[4 * k + 0], a0);
            a1 = fmaf(hv[k].y, w[4 * k + 1], a1);
            a2 = fmaf(hv[k].z, w[4 * k + 2], a2);
            a3 = fmaf(hv[k].w, w[4 * k + 3], a3);
        }
        float s = (xe + bhv) + ((a0 + a1) + (a2 + a3));

        // prefetch next embedding while tanh runs
        xe = sWxh[tokn * HH + lane];

        const float h = htanh(s);
        sH[(t + 1) & 1][warp][lane] = h;   // write NEW buffer (disjoint from reads)
        outp[(long)t * (BB * HH)] = h;     // coalesced 128B per warp
        __syncwarp();
    }
}

// ---------------------------------------------------------------------------
// packed f32x2 helpers (sm_100+: fma.rn.f32x2 — 2x fp32 throughput vs FFMA)
// ---------------------------------------------------------------------------
__device__ __forceinline__ unsigned long long splat2(float x) {
    unsigned long long r;
    asm("mov.b64 %0, {%1, %1};" : "=l"(r) : "f"(x));
    return r;
}
__device__ __forceinline__ unsigned long long pack2(float x, float y) {
    unsigned long long r;
    asm("mov.b64 %0, {%1, %2};" : "=l"(r) : "f"(x), "f"(y));
    return r;
}
__device__ __forceinline__ unsigned long long fma2(unsigned long long a,
                                                   unsigned long long b,
                                                   unsigned long long c) {
    unsigned long long d;
    asm("fma.rn.f32x2 %0, %1, %2, %3;" : "=l"(d) : "l"(a), "l"(b), "l"(c));
    return d;
}
__device__ __forceinline__ float2 unpack2(unsigned long long u) {
    float2 f;
    asm("mov.b64 {%0, %1}, %2;" : "=f"(f.x), "=f"(f.y) : "l"(u));
    return f;
}

// ---------------------------------------------------------------------------
// Kernel B: logits[b][t][v] = sum_h hs[t][b][h] * Whq[h][v] + bq[v]
// 512 threads / 16 warps, 128 rows per block (2 chunks of 4 rows per warp).
// Lane L owns contiguous v in [8L, 8L+8): W read as 2x LDS.128 per k,
// h read as 1x LDS.128 broadcast per row per 4 k's, splat on ALU pipe.
// No shuffles. Bias folded into accumulator init.
// ---------------------------------------------------------------------------
__global__ void __launch_bounds__(512)
rnn_logits(const float* __restrict__ Whq, const float* __restrict__ bq,
           float* __restrict__ out)
{
    __shared__ float sW[HH * VV];      // 32 KB  [h][v]
    __shared__ float sHs[128 * HH];    // 16 KB  this block's 128 hs rows

    const int tid  = threadIdx.x;
    const int lane = tid & 31;
    const int warp = tid >> 5;

    // stage W
    {
        const float4* s = (const float4*)Whq;
        float4*       d = (float4*)sW;
        #pragma unroll
        for (int i = tid; i < (HH * VV) / 4; i += 512) d[i] = s[i];
    }
    // stage 128 hs rows
    {
        const float4* s = (const float4*)(g_hs + (long)blockIdx.x * 128 * HH);
        float4*       d = (float4*)sHs;
        #pragma unroll
        for (int i = tid; i < (128 * HH) / 4; i += 512) d[i] = s[i];
    }

    // bias pairs for this lane's v range [8L, 8L+8)
    float4 bq0 = ((const float4*)bq)[lane * 2 + 0];
    float4 bq1 = ((const float4*)bq)[lane * 2 + 1];
    const unsigned long long bp0 = pack2(bq0.x, bq0.y);
    const unsigned long long bp1 = pack2(bq0.z, bq0.w);
    const unsigned long long bp2 = pack2(bq1.x, bq1.y);
    const unsigned long long bp3 = pack2(bq1.z, bq1.w);

    __syncthreads();

    const float4* sW4  = (const float4*)sW;    // 64 float4 per h-row
    const float4* sHs4 = (const float4*)sHs;   // 8 float4 per hs-row

    #pragma unroll
    for (int c = 0; c < 2; c++) {
        const int lrow0 = (warp * 2 + c) * 4;          // local row base

        unsigned long long acc[4][4];
        #pragma unroll
        for (int r = 0; r < 4; r++) {
            acc[r][0] = bp0; acc[r][1] = bp1; acc[r][2] = bp2; acc[r][3] = bp3;
        }

        #pragma unroll
        for (int i4 = 0; i4 < HH / 4; i4++) {
            // h[r][4*i4 .. 4*i4+3] via broadcast LDS.128
            float4 h4[4];
            #pragma unroll
            for (int r = 0; r < 4; r++) h4[r] = sHs4[(lrow0 + r) * 8 + i4];

            #pragma unroll
            for (int ii = 0; ii < 4; ii++) {
                const int i = 4 * i4 + ii;
                const float4 wa = sW4[i * 64 + lane * 2 + 0];
                const float4 wb = sW4[i * 64 + lane * 2 + 1];
                const unsigned long long w0 = pack2(wa.x, wa.y);
                const unsigned long long w1 = pack2(wa.z, wa.w);
                const unsigned long long w2 = pack2(wb.x, wb.y);
                const unsigned long long w3 = pack2(wb.z, wb.w);

                #pragma unroll
                for (int r = 0; r < 4; r++) {
                    const float hs = (ii == 0) ? h4[r].x :
                                     (ii == 1) ? h4[r].y :
                                     (ii == 2) ? h4[r].z : h4[r].w;
                    const unsigned long long hh = splat2(hs);
                    acc[r][0] = fma2(hh, w0, acc[r][0]);
                    acc[r][1] = fma2(hh, w1, acc[r][1]);
                    acc[r][2] = fma2(hh, w2, acc[r][2]);
                    acc[r][3] = fma2(hh, w3, acc[r][3]);
                }
            }
        }

        // store: lane L writes v = 8L .. 8L+7 as 2x STG.128
        #pragma unroll
        for (int r = 0; r < 4; r++) {
            const long row = (long)blockIdx.x * 128 + lrow0 + r;  // row = t*B + b
            const int  t   = (int)(row >> 10);                    // B = 1024
            const int  b   = (int)(row & 1023);
            float4* o = (float4*)(out + (((long)b * TT + t) * VV) + 8 * lane);
            const float2 f0 = unpack2(acc[r][0]);
            const float2 f1 = unpack2(acc[r][1]);
            const float2 f2 = unpack2(acc[r][2]);
            const float2 f3 = unpack2(acc[r][3]);
            o[0] = make_float4(f0.x, f0.y, f1.x, f1.y);
            o[1] = make_float4(f2.x, f2.y, f3.x, f3.y);
        }
    }
}

// ---------------------------------------------------------------------------
// kernel_launch
// inputs: 0:X int32[B,T]  1:W_xh f32[V,H]  2:W_hh f32[H,H]  3:b_h f32[H]
//         4:W_hq f32[H,V] 5:b_q f32[V]     out: f32[B,T,V]
// ---------------------------------------------------------------------------
extern "C" void kernel_launch(void* const* d_in, const int* in_sizes, int n_in,
                              void* d_out, int out_size)
{
    const int*   X   = (const int*)d_in[0];
    const float* Wxh = (const float*)d_in[1];
    const float* Whh = (const float*)d_in[2];
    const float* bh  = (const float*)d_in[3];
    const float* Whq = (const float*)d_in[4];
    const float* bq  = (const float*)d_in[5];
    float*       out = (float*)d_out;

    rnn_recurrence<<<BB / 8, 256>>>(X, Wxh, Whh, bh);
    rnn_logits<<<(TT * BB) / 128, 512>>>(Whq, bq, out);
}

// round 3
// speedup vs baseline: 2.8858x; 2.8858x over previous
#include <cuda_runtime.h>
#include <cuda_bf16.h>

#define BB 1024
#define TT 256
#define VV 256
#define HH 32

// hs scratch, layout [t][b][h]  (row r = t*B + b is contiguous 32 floats)
__device__ float g_hs[TT * BB * HH];

__device__ __forceinline__ float htanh(float x) {
    float y;
    asm("tanh.approx.f32 %0, %1;" : "=f"(y) : "f"(x));
    return y;
}

// ---------------------------------------------------------------------------
// Kernel A: embedding gather + recurrence (unchanged from round 2: ~26us).
// One warp per batch element, h[j] in lane j; h broadcast via double-buffered
// SMEM vector (1 STS + 1 WARPSYNC + 8 LDS.128 per step), tanh.approx MUFU.
// ---------------------------------------------------------------------------
__global__ void __launch_bounds__(256)
rnn_recurrence(const int* __restrict__ X, const float* __restrict__ Wxh,
               const float* __restrict__ Whh, const float* __restrict__ bh)
{
    __shared__ float sWxh[VV * HH];       // 32 KB
    __shared__ int   sX[8][TT];           // 8 KB
    __shared__ float sH[2][8][HH];        // 2 KB double-buffered h vectors

    const int tid  = threadIdx.x;
    const int lane = tid & 31;
    const int warp = tid >> 5;
    const int b    = blockIdx.x * 8 + warp;

    {
        const float4* s = (const float4*)Wxh;
        float4*       d = (float4*)sWxh;
        #pragma unroll
        for (int i = tid; i < (VV * HH) / 4; i += 256) d[i] = s[i];
    }
    {
        const int4* s = (const int4*)(X + (long)blockIdx.x * 8 * TT);
        int4*       d = (int4*)&sX[0][0];
        #pragma unroll
        for (int i = tid; i < (8 * TT) / 4; i += 256) d[i] = s[i];
    }

    float w[HH];
    #pragma unroll
    for (int i = 0; i < HH; i++) w[i] = Whh[i * HH + lane];
    const float bhv = bh[lane];

    sH[0][warp][lane] = 0.f;
    __syncthreads();

    float* outp = g_hs + (long)b * HH + lane;

    int   tok = sX[warp][0];
    float xe  = sWxh[tok * HH + lane];

    #pragma unroll 2
    for (int t = 0; t < TT; t++) {
        const int tokn = sX[warp][(t + 1) & (TT - 1)];

        const float4* hr = (const float4*)&sH[t & 1][warp][0];
        float4 hv[8];
        #pragma unroll
        for (int k = 0; k < 8; k++) hv[k] = hr[k];

        float a0 = 0.f, a1 = 0.f, a2 = 0.f, a3 = 0.f;
        #pragma unroll
        for (int k = 0; k < 8; k++) {
            a0 = fmaf(hv[k].x, w[4 * k + 0], a0);
            a1 = fmaf(hv[k].y, w[4 * k + 1], a1);
            a2 = fmaf(hv[k].z, w[4 * k + 2], a2);
            a3 = fmaf(hv[k].w, w[4 * k + 3], a3);
        }
        float s = (xe + bhv) + ((a0 + a1) + (a2 + a3));

        xe = sWxh[tokn * HH + lane];

        const float h = htanh(s);
        sH[(t + 1) & 1][warp][lane] = h;
        outp[(long)t * (BB * HH)] = h;
        __syncwarp();
    }
}

// ---------------------------------------------------------------------------
// packed f32x2 helpers
// ---------------------------------------------------------------------------
__device__ __forceinline__ unsigned long long splat2(float x) {
    unsigned long long r;
    asm("mov.b64 %0, {%1, %1};" : "=l"(r) : "f"(x));
    return r;
}
__device__ __forceinline__ unsigned long long fma2(unsigned long long a,
                                                   unsigned long long b,
                                                   unsigned long long c) {
    unsigned long long d;
    asm("fma.rn.f32x2 %0, %1, %2, %3;" : "=l"(d) : "l"(a), "l"(b), "l"(c));
    return d;
}
__device__ __forceinline__ float2 unpack2(unsigned long long u) {
    float2 f;
    asm("mov.b64 {%0, %1}, %2;" : "=f"(f.x), "=f"(f.y) : "l"(u));
    return f;
}

// ---------------------------------------------------------------------------
// Kernel B: logits[b][t][v] = sum_h hs[t][b][h] * Whq[h][v] + bq[v]
// Round-1 skeleton (256 thr / 8 warps / 4 rows per warp / 32 rows per block,
// lane owns v-pairs v = 2*(lane+32j)), with the ONLY change being:
// h comes from a staged SMEM tile via broadcast LDS.128 (1 per row per 4 k)
// instead of 4 SHFLs per k. Bias folded into acc init (kills epilogue LDS).
// ---------------------------------------------------------------------------
__global__ void __launch_bounds__(256)
rnn_logits(const float* __restrict__ Whq, const float* __restrict__ bq,
           float* __restrict__ out)
{
    __shared__ float sW[HH * VV];     // 32 KB, [h][v]
    __shared__ float sHs[32 * HH];    // 4 KB, this block's 32 hs rows

    const int tid  = threadIdx.x;
    const int lane = tid & 31;
    const int warp = tid >> 5;

    {
        const float4* s = (const float4*)Whq;
        float4*       d = (float4*)sW;
        #pragma unroll
        for (int i = tid; i < (HH * VV) / 4; i += 256) d[i] = s[i];
    }
    {
        const float4* s = (const float4*)(g_hs + (long)blockIdx.x * 32 * HH);
        float4*       d = (float4*)sHs;
        d[tid] = s[tid];   // 256 float4 = exactly one pass
    }

    // bias pairs for this lane's v set (from global; L2-resident)
    const unsigned long long* bq2 = (const unsigned long long*)bq;
    unsigned long long bp0 = bq2[lane +  0];
    unsigned long long bp1 = bq2[lane + 32];
    unsigned long long bp2 = bq2[lane + 64];
    unsigned long long bp3 = bq2[lane + 96];

    __syncthreads();

    const int lrow0 = warp * 4;

    const unsigned long long* sW2  = (const unsigned long long*)sW;   // 128/h-row
    const float4*             sHs4 = (const float4*)sHs;              // 8/hs-row

    unsigned long long acc[4][4];
    #pragma unroll
    for (int r = 0; r < 4; r++) {
        acc[r][0] = bp0; acc[r][1] = bp1; acc[r][2] = bp2; acc[r][3] = bp3;
    }

    #pragma unroll
    for (int i4 = 0; i4 < HH / 4; i4++) {
        // h[r][4*i4 .. 4*i4+3] via broadcast LDS.128 (replaces SHFLs)
        float4 h4[4];
        #pragma unroll
        for (int r = 0; r < 4; r++) h4[r] = sHs4[(lrow0 + r) * 8 + i4];

        #pragma unroll
        for (int ii = 0; ii < 4; ii++) {
            const int i = 4 * i4 + ii;
            const unsigned long long w0 = sW2[i * 128 + lane];
            const unsigned long long w1 = sW2[i * 128 + lane + 32];
            const unsigned long long w2 = sW2[i * 128 + lane + 64];
            const unsigned long long w3 = sW2[i * 128 + lane + 96];

            #pragma unroll
            for (int r = 0; r < 4; r++) {
                const float hs = (ii == 0) ? h4[r].x :
                                 (ii == 1) ? h4[r].y :
                                 (ii == 2) ? h4[r].z : h4[r].w;
                const unsigned long long hh = splat2(hs);
                acc[r][0] = fma2(hh, w0, acc[r][0]);
                acc[r][1] = fma2(hh, w1, acc[r][1]);
                acc[r][2] = fma2(hh, w2, acc[r][2]);
                acc[r][3] = fma2(hh, w3, acc[r][3]);
            }
        }
    }

    #pragma unroll
    for (int r = 0; r < 4; r++) {
        const long row = (long)blockIdx.x * 32 + lrow0 + r;  // row = t*B + b
        const int  t   = (int)(row >> 10);                    // B = 1024
        const int  b   = (int)(row & 1023);
        float2* o = (float2*)(out + (((long)b * TT + t) * VV));
        #pragma unroll
        for (int j = 0; j < 4; j++) {
            o[lane + 32 * j] = unpack2(acc[r][j]);  // coalesced 256B per j
        }
    }
}

// ---------------------------------------------------------------------------
// kernel_launch
// inputs: 0:X int32[B,T]  1:W_xh f32[V,H]  2:W_hh f32[H,H]  3:b_h f32[H]
//         4:W_hq f32[H,V] 5:b_q f32[V]     out: f32[B,T,V]
// ---------------------------------------------------------------------------
extern "C" void kernel_launch(void* const* d_in, const int* in_sizes, int n_in,
                              void* d_out, int out_size)
{
    const int*   X   = (const int*)d_in[0];
    const float* Wxh = (const float*)d_in[1];
    const float* Whh = (const float*)d_in[2];
    const float* bh  = (const float*)d_in[3];
    const float* Whq = (const float*)d_in[4];
    const float* bq  = (const float*)d_in[5];
    float*       out = (float*)d_out;

    rnn_recurrence<<<BB / 8, 256>>>(X, Wxh, Whh, bh);
    rnn_logits<<<(TT * BB) / 32, 256>>>(Whq, bq, out);
}